// round 1
// baseline (speedup 1.0000x reference)
#include <cuda_runtime.h>
#include <math.h>

#define C_IN   64
#define FD     8
#define OUTC   9
#define KW     5
#define WOUT   4
#define HEIGHT 4096
#define BATCH  32
#define NTOK   (BATCH * HEIGHT)      // 131072 tokens (b,h)
#define HALF   36
#define MIN_EIG 0.001f
#define NSWEEP 6

// SoA scratch: sigma[e][token], e = o*4 + w  (e-th upper-tri entry)
__device__ float g_sigma[HALF * NTOK];

__device__ __forceinline__ float softplus(float v) {
    // matches jax.nn.softplus to well within tolerance
    return v > 20.0f ? v : log1pf(expf(v));
}

// ---------------------------------------------------------------------------
// Kernel 1: fused 1x1 conv (loc) + (1,5) valid conv (sigma entries)
// One thread = one (b,h) token. 188 FMA per channel step, 64 steps.
// ---------------------------------------------------------------------------
__global__ void __launch_bounds__(256) conv_kernel(
    const float* __restrict__ x,   // [B, C_IN, H, FD]
    const float* __restrict__ wn,  // [C_IN]
    const float* __restrict__ bn,  // [1]
    const float* __restrict__ wp,  // [OUTC, C_IN, 1, KW]
    const float* __restrict__ bp,  // [OUTC]
    float* __restrict__ out_loc)   // [NTOK, FD]
{
    __shared__ float s_wp[OUTC * C_IN * KW];
    __shared__ float s_wn[C_IN];
    __shared__ float s_b[OUTC + 1];

    const int t = threadIdx.x;
    for (int i = t; i < OUTC * C_IN * KW; i += 256) s_wp[i] = wp[i];
    if (t < C_IN) s_wn[t] = wn[t];
    if (t < OUTC) s_b[t] = bp[t];
    if (t == 0)   s_b[OUTC] = bn[0];
    __syncthreads();

    const int tok = blockIdx.x * 256 + t;
    const int b = tok >> 12;          // H = 4096
    const int h = tok & (HEIGHT - 1);

    const float* xb = x + (size_t)b * (C_IN * HEIGHT * FD) + (size_t)h * FD;

    float accL[FD];
    float accP[HALF];
#pragma unroll
    for (int j = 0; j < FD; j++) accL[j] = 0.0f;
#pragma unroll
    for (int e = 0; e < HALF; e++) accP[e] = 0.0f;

#pragma unroll 4
    for (int c = 0; c < C_IN; c++) {
        const float4* p4 = (const float4*)(xb + (size_t)c * (HEIGHT * FD));
        float4 u = p4[0];
        float4 v = p4[1];
        float xv[8] = {u.x, u.y, u.z, u.w, v.x, v.y, v.z, v.w};

        const float w0 = s_wn[c];
#pragma unroll
        for (int j = 0; j < FD; j++) accL[j] = fmaf(xv[j], w0, accL[j]);

#pragma unroll
        for (int o = 0; o < OUTC; o++) {
            const float* wr = s_wp + (o * C_IN + c) * KW;
            float w[KW];
#pragma unroll
            for (int k = 0; k < KW; k++) w[k] = wr[k];
#pragma unroll
            for (int ww = 0; ww < WOUT; ww++) {
#pragma unroll
                for (int k = 0; k < KW; k++)
                    accP[o * WOUT + ww] = fmaf(xv[ww + k], w[k], accP[o * WOUT + ww]);
            }
        }
    }

    const float bnv = s_b[OUTC];
    float4 lo, hi;
    lo.x = softplus(accL[0] + bnv); lo.y = softplus(accL[1] + bnv);
    lo.z = softplus(accL[2] + bnv); lo.w = softplus(accL[3] + bnv);
    hi.x = softplus(accL[4] + bnv); hi.y = softplus(accL[5] + bnv);
    hi.z = softplus(accL[6] + bnv); hi.w = softplus(accL[7] + bnv);
    float4* lp = (float4*)(out_loc + (size_t)tok * FD);
    lp[0] = lo; lp[1] = hi;

#pragma unroll
    for (int e = 0; e < HALF; e++)
        g_sigma[e * NTOK + tok] = softplus(accP[e] + s_b[e >> 2]);
}

// ---------------------------------------------------------------------------
// Kernel 2: batched 8x8 symmetric eigh via fixed-sweep cyclic Jacobi,
// eigenvalue clamp, PD reconstruction. One thread = one matrix.
// Branch-free rotation: |denom| >= 2|apq| guarantees |t| <= 1 always.
// ---------------------------------------------------------------------------
__global__ void __launch_bounds__(128) eigh_kernel(float* __restrict__ out_pd)
{
    const int tok = blockIdx.x * 128 + threadIdx.x;

    float s[HALF];
#pragma unroll
    for (int e = 0; e < HALF; e++) s[e] = g_sigma[e * NTOK + tok];

    float A[8][8];
    float V[8][8];
    {
        int e = 0;
#pragma unroll
        for (int i = 0; i < 8; i++)
#pragma unroll
            for (int j = i; j < 8; j++) { A[i][j] = s[e]; A[j][i] = s[e]; e++; }
    }
#pragma unroll
    for (int i = 0; i < 8; i++)
#pragma unroll
        for (int j = 0; j < 8; j++) V[i][j] = (i == j) ? 1.0f : 0.0f;

#pragma unroll 1
    for (int sweep = 0; sweep < NSWEEP; sweep++) {
#pragma unroll
        for (int p = 0; p < 7; p++) {
#pragma unroll
            for (int q = p + 1; q < 8; q++) {
                float apq = A[p][q];
                float tau = A[q][q] - A[p][p];
                float r   = sqrtf(fmaf(tau, tau, 4.0f * apq * apq));
                float dn  = tau + copysignf(r, tau);
                dn += copysignf(1e-30f, dn);          // only matters when apq==tau==0
                float tt = (2.0f * apq) / dn;         // |tt| <= 1
                float cc = rsqrtf(fmaf(tt, tt, 1.0f));
                float ss = tt * cc;

                A[p][p] = fmaf(-tt, apq, A[p][p]);
                A[q][q] = fmaf( tt, apq, A[q][q]);
                A[p][q] = 0.0f; A[q][p] = 0.0f;

#pragma unroll
                for (int j = 0; j < 8; j++) {
                    if (j == p || j == q) continue;
                    float ajp = A[j][p], ajq = A[j][q];
                    float np = cc * ajp - ss * ajq;
                    float nq = ss * ajp + cc * ajq;
                    A[j][p] = np; A[p][j] = np;
                    A[j][q] = nq; A[q][j] = nq;
                }
#pragma unroll
                for (int j = 0; j < 8; j++) {
                    float vjp = V[j][p], vjq = V[j][q];
                    V[j][p] = cc * vjp - ss * vjq;
                    V[j][q] = ss * vjp + cc * vjq;
                }
            }
        }
    }

    float lam[8];
#pragma unroll
    for (int k = 0; k < 8; k++) lam[k] = fmaxf(A[k][k], MIN_EIG);

    float W[8][8];
#pragma unroll
    for (int i = 0; i < 8; i++)
#pragma unroll
        for (int k = 0; k < 8; k++) W[i][k] = V[i][k] * lam[k];

    float pd[8][8];
#pragma unroll
    for (int i = 0; i < 8; i++) {
#pragma unroll
        for (int j = i; j < 8; j++) {
            float acc = 0.0f;
#pragma unroll
            for (int k = 0; k < 8; k++) acc = fmaf(W[i][k], V[j][k], acc);
            pd[i][j] = acc; pd[j][i] = acc;
        }
    }

    float* o = out_pd + (size_t)tok * 64;
#pragma unroll
    for (int i = 0; i < 8; i++) {
        float4 a, b2;
        a.x = pd[i][0]; a.y = pd[i][1]; a.z = pd[i][2]; a.w = pd[i][3];
        b2.x = pd[i][4]; b2.y = pd[i][5]; b2.z = pd[i][6]; b2.w = pd[i][7];
        ((float4*)o)[i * 2]     = a;
        ((float4*)o)[i * 2 + 1] = b2;
    }
}

// ---------------------------------------------------------------------------
extern "C" void kernel_launch(void* const* d_in, const int* in_sizes, int n_in,
                              void* d_out, int out_size)
{
    // Identify inputs by element count (robust to metadata ordering):
    // x: 67108864, w_n: 64, b_n: 1, w_p: 2880, b_p: 9
    const float* x  = nullptr;
    const float* wn = nullptr;
    const float* bn = nullptr;
    const float* wp = nullptr;
    const float* bp = nullptr;
    for (int i = 0; i < n_in; i++) {
        switch (in_sizes[i]) {
            case 64:    wn = (const float*)d_in[i]; break;
            case 1:     bn = (const float*)d_in[i]; break;
            case 2880:  wp = (const float*)d_in[i]; break;
            case 9:     bp = (const float*)d_in[i]; break;
            default:    x  = (const float*)d_in[i]; break;
        }
    }

    float* out = (float*)d_out;
    float* loc = out;                                   // [B,1,H,FD] at front
    float* pd  = out + ((size_t)out_size - (size_t)NTOK * 64);  // [B,1,H,8,8] at back

    conv_kernel<<<NTOK / 256, 256>>>(x, wn, bn, wp, bp, loc);
    eigh_kernel<<<NTOK / 128, 128>>>(pd);
}

// round 2
// speedup vs baseline: 1.0853x; 1.0853x over previous
#include <cuda_runtime.h>
#include <math.h>

#define C_IN   64
#define FD     8
#define OUTC   9
#define KW     5
#define WOUT   4
#define HEIGHT 4096
#define BATCH  32
#define NTOK   (BATCH * HEIGHT)      // 131072 tokens (b,h)
#define NPAIR  (NTOK / 2)
#define HALF   36
#define MIN_EIG 0.001f
#define NSWEEP 4

// SoA scratch: sigma[e][token], e-th upper-tri entry (row-major triu order)
__device__ float g_sigma[HALF * NTOK];

typedef unsigned long long ull;

__device__ __forceinline__ ull pk(float lo, float hi) {
    ull r;
    asm("mov.b64 %0, {%1, %2};" : "=l"(r) : "f"(lo), "f"(hi));
    return r;
}
__device__ __forceinline__ void upk(ull v, float& lo, float& hi) {
    asm("mov.b64 {%0, %1}, %2;" : "=f"(lo), "=f"(hi) : "l"(v));
}
__device__ __forceinline__ ull fma2(ull a, ull b, ull c) {
    ull d;
    asm("fma.rn.f32x2 %0, %1, %2, %3;" : "=l"(d) : "l"(a), "l"(b), "l"(c));
    return d;
}

__device__ __forceinline__ float softplus(float v) {
    return v > 20.0f ? v : log1pf(expf(v));
}

// ---------------------------------------------------------------------------
// Kernel 1: fused 1x1 conv (loc) + (1,5) valid conv (sigma entries).
// One thread = TWO adjacent (b,h) tokens, packed into f32x2 lanes so every
// FMA is an FFMA2 (2x FFMA throughput on sm_103a).
// ---------------------------------------------------------------------------
__global__ void __launch_bounds__(128, 4) conv_kernel(
    const float* __restrict__ x,   // [B, C_IN, H, FD]
    const float* __restrict__ wn,  // [C_IN]
    const float* __restrict__ bn,  // [1]
    const float* __restrict__ wp,  // [OUTC, C_IN, 1, KW]
    const float* __restrict__ bp,  // [OUTC]
    float* __restrict__ out_loc)   // [NTOK, FD]
{
    __shared__ ull  s_wp2[OUTC * C_IN * KW];   // broadcast-packed weights
    __shared__ ull  s_wn2[C_IN];
    __shared__ float s_b[OUTC + 1];

    const int t = threadIdx.x;
    for (int i = t; i < OUTC * C_IN * KW; i += 128) {
        float w = wp[i];
        s_wp2[i] = pk(w, w);
    }
    if (t < C_IN) { float w = wn[t]; s_wn2[t] = pk(w, w); }
    if (t < OUTC) s_b[t] = bp[t];
    if (t == 0)   s_b[OUTC] = bn[0];
    __syncthreads();

    const int pair = blockIdx.x * 128 + t;     // 0 .. NPAIR-1
    const int t0 = pair * 2;                   // even token
    const int b  = t0 >> 12;                   // H = 4096
    const int h  = t0 & (HEIGHT - 1);

    const float* xb = x + (size_t)b * (C_IN * HEIGHT * FD) + (size_t)h * FD;

    ull accL[FD];
    ull accP[HALF];
#pragma unroll
    for (int j = 0; j < FD; j++) accL[j] = 0ULL;
#pragma unroll
    for (int e = 0; e < HALF; e++) accP[e] = 0ULL;

#pragma unroll 2
    for (int c = 0; c < C_IN; c++) {
        // 16 contiguous floats: token t0 row (8) then token t0+1 row (8)
        const float4* p4 = (const float4*)(xb + (size_t)c * (HEIGHT * FD));
        float4 u0 = p4[0], u1 = p4[1], v0 = p4[2], v1 = p4[3];
        float x0[8] = {u0.x, u0.y, u0.z, u0.w, u1.x, u1.y, u1.z, u1.w};
        float x1[8] = {v0.x, v0.y, v0.z, v0.w, v1.x, v1.y, v1.z, v1.w};
        ull xp[8];
#pragma unroll
        for (int f = 0; f < 8; f++) xp[f] = pk(x0[f], x1[f]);

        const ull w0 = s_wn2[c];
#pragma unroll
        for (int j = 0; j < FD; j++) accL[j] = fma2(xp[j], w0, accL[j]);

#pragma unroll
        for (int o = 0; o < OUTC; o++) {
            const ull* wr = s_wp2 + (o * C_IN + c) * KW;
            ull w[KW];
#pragma unroll
            for (int k = 0; k < KW; k++) w[k] = wr[k];
#pragma unroll
            for (int ww = 0; ww < WOUT; ww++) {
#pragma unroll
                for (int k = 0; k < KW; k++)
                    accP[o * WOUT + ww] = fma2(xp[ww + k], w[k], accP[o * WOUT + ww]);
            }
        }
    }

    // epilogue: loc = softplus(acc + b_n), both tokens (16 contiguous floats)
    const float bnv = s_b[OUTC];
    float r0[8], r1[8];
#pragma unroll
    for (int j = 0; j < FD; j++) {
        float a, bb;
        upk(accL[j], a, bb);
        r0[j] = softplus(a + bnv);
        r1[j] = softplus(bb + bnv);
    }
    float4* lp = (float4*)(out_loc + (size_t)t0 * FD);
    lp[0] = make_float4(r0[0], r0[1], r0[2], r0[3]);
    lp[1] = make_float4(r0[4], r0[5], r0[6], r0[7]);
    lp[2] = make_float4(r1[0], r1[1], r1[2], r1[3]);
    lp[3] = make_float4(r1[4], r1[5], r1[6], r1[7]);

    // sigma entries -> SoA scratch, two adjacent tokens = one float2 store
#pragma unroll
    for (int e = 0; e < HALF; e++) {
        float a, bb;
        upk(accP[e], a, bb);
        float be = s_b[e >> 2];
        float2 sv = make_float2(softplus(a + be), softplus(bb + be));
        *(float2*)(g_sigma + (size_t)e * NTOK + t0) = sv;
    }
}

// ---------------------------------------------------------------------------
// Kernel 2: batched 8x8 symmetric eigh via fixed-sweep cyclic Jacobi.
// A kept as 36-entry upper triangle (compile-time-folded indexing).
// Division-free rotation: 2 rsqrt, trace-preserving diagonal update.
// ---------------------------------------------------------------------------
#define TI(i,j) ((i) <= (j) ? ((i)*(17-(i)))/2 + ((j)-(i)) \
                            : ((j)*(17-(j)))/2 + ((i)-(j)))
#define AT(i,j) Au[TI(i,j)]

__global__ void __launch_bounds__(128) eigh_kernel(float* __restrict__ out_pd)
{
    const int tok = blockIdx.x * 128 + threadIdx.x;

    float Au[HALF];
#pragma unroll
    for (int e = 0; e < HALF; e++) Au[e] = g_sigma[e * NTOK + tok];

    float V[8][8];
#pragma unroll
    for (int i = 0; i < 8; i++)
#pragma unroll
        for (int j = 0; j < 8; j++) V[i][j] = (i == j) ? 1.0f : 0.0f;

#pragma unroll 1
    for (int sweep = 0; sweep < NSWEEP; sweep++) {
#pragma unroll
        for (int p = 0; p < 7; p++) {
#pragma unroll
            for (int q = p + 1; q < 8; q++) {
                float apq = AT(p, q);
                float app = AT(p, p);
                float aqq = AT(q, q);
                float tau = (aqq - app);
                tau += copysignf(1e-18f, tau);          // degenerate-safe
                float r2    = fmaf(tau, tau, 4.0f * apq * apq);
                float inv_r = rsqrtf(r2);
                float c2    = fmaf(0.5f * fabsf(tau), inv_r, 0.5f); // cos^2
                float cinv  = rsqrtf(c2);
                float cc    = c2 * cinv;                            // cos
                float st    = (tau < 0.0f) ? -apq : apq;            // sign(tau)*apq
                float ss    = st * inv_r * cinv;                    // sin
                float s2c   = 2.0f * st * inv_r;                    // sin(2phi)*sign fold

                float napp = c2 * app + (1.0f - c2) * aqq - s2c * apq;
                AT(p, p) = napp;
                AT(q, q) = (app + aqq) - napp;
                AT(p, q) = 0.0f;

#pragma unroll
                for (int j = 0; j < 8; j++) {
                    if (j == p || j == q) continue;
                    float ajp = AT(j, p), ajq = AT(j, q);
                    AT(j, p) = cc * ajp - ss * ajq;
                    AT(j, q) = ss * ajp + cc * ajq;
                }
#pragma unroll
                for (int j = 0; j < 8; j++) {
                    float vjp = V[j][p], vjq = V[j][q];
                    V[j][p] = cc * vjp - ss * vjq;
                    V[j][q] = ss * vjp + cc * vjq;
                }
            }
        }
    }

    float lam[8];
#pragma unroll
    for (int k = 0; k < 8; k++) lam[k] = fmaxf(AT(k, k), MIN_EIG);

    float W[8][8];
#pragma unroll
    for (int i = 0; i < 8; i++)
#pragma unroll
        for (int k = 0; k < 8; k++) W[i][k] = V[i][k] * lam[k];

    float pd[8][8];
#pragma unroll
    for (int i = 0; i < 8; i++) {
#pragma unroll
        for (int j = i; j < 8; j++) {
            float acc = 0.0f;
#pragma unroll
            for (int k = 0; k < 8; k++) acc = fmaf(W[i][k], V[j][k], acc);
            pd[i][j] = acc; pd[j][i] = acc;
        }
    }

    float* o = out_pd + (size_t)tok * 64;
#pragma unroll
    for (int i = 0; i < 8; i++) {
        ((float4*)o)[i * 2]     = make_float4(pd[i][0], pd[i][1], pd[i][2], pd[i][3]);
        ((float4*)o)[i * 2 + 1] = make_float4(pd[i][4], pd[i][5], pd[i][6], pd[i][7]);
    }
}

// ---------------------------------------------------------------------------
extern "C" void kernel_launch(void* const* d_in, const int* in_sizes, int n_in,
                              void* d_out, int out_size)
{
    // Identify inputs by element count (robust to metadata ordering):
    // x: 67108864, w_n: 64, b_n: 1, w_p: 2880, b_p: 9
    const float* x  = nullptr;
    const float* wn = nullptr;
    const float* bn = nullptr;
    const float* wp = nullptr;
    const float* bp = nullptr;
    for (int i = 0; i < n_in; i++) {
        switch (in_sizes[i]) {
            case 64:    wn = (const float*)d_in[i]; break;
            case 1:     bn = (const float*)d_in[i]; break;
            case 2880:  wp = (const float*)d_in[i]; break;
            case 9:     bp = (const float*)d_in[i]; break;
            default:    x  = (const float*)d_in[i]; break;
        }
    }

    float* out = (float*)d_out;
    float* loc = out;                                            // [B,1,H,FD]
    float* pd  = out + ((size_t)out_size - (size_t)NTOK * 64);   // [B,1,H,8,8]

    conv_kernel<<<NPAIR / 128, 128>>>(x, wn, bn, wp, bp, loc);
    eigh_kernel<<<NTOK / 128, 128>>>(pd);
}

// round 3
// speedup vs baseline: 1.4187x; 1.3072x over previous
#include <cuda_runtime.h>
#include <math.h>

#define C_IN   64
#define FD     8
#define OUTC   9
#define KW     5
#define WOUT   4
#define HEIGHT 4096
#define BATCH  32
#define NTOK   (BATCH * HEIGHT)      // 131072 tokens (b,h)
#define HALF   36
#define MIN_EIG 0.001f
#define NSWEEP 4

// SoA scratch: sigma[e][token], e-th upper-tri entry (row-major triu order)
__device__ float g_sigma[HALF * NTOK];

typedef unsigned long long ull;

__device__ __forceinline__ ull pk(float lo, float hi) {
    ull r;
    asm("mov.b64 %0, {%1, %2};" : "=l"(r) : "f"(lo), "f"(hi));
    return r;
}
__device__ __forceinline__ void upk(ull v, float& lo, float& hi) {
    asm("mov.b64 {%0, %1}, %2;" : "=f"(lo), "=f"(hi) : "l"(v));
}
__device__ __forceinline__ ull fma2(ull a, ull b, ull c) {
    ull d;
    asm("fma.rn.f32x2 %0, %1, %2, %3;" : "=l"(d) : "l"(a), "l"(b), "l"(c));
    return d;
}

__device__ __forceinline__ float softplus(float v) {
    return v > 20.0f ? v : log1pf(expf(v));
}

// ---------------------------------------------------------------------------
// Kernel 1: fused 1x1 conv (loc) + (1,5) valid conv (sigma entries).
// One thread = ONE token; FFMA2 packing across adjacent FEATURE positions:
// output pair (w, w+1) shares the broadcast weight, so
//   fma2( pk(x[w+k], x[w+1+k]), pk(w_k, w_k), acc )
// produces both outputs. 94 FFMA2 per channel, ~44 accumulator regs.
// Weights pre-packed+padded in SMEM: 6 ULL per (o,c) -> 2x LDS.128 + LDS.64.
// ---------------------------------------------------------------------------
__global__ void __launch_bounds__(256) conv_kernel(
    const float* __restrict__ x,   // [B, C_IN, H, FD]
    const float* __restrict__ wn,  // [C_IN]
    const float* __restrict__ bn,  // [1]
    const float* __restrict__ wp,  // [OUTC, C_IN, 1, KW]
    const float* __restrict__ bp,  // [OUTC]
    float* __restrict__ out_loc)   // [NTOK, FD]
{
    __shared__ ull  s_wp2[OUTC * C_IN * 6];    // broadcast-packed, padded to 6
    __shared__ ull  s_wn2[C_IN];
    __shared__ float s_b[OUTC + 1];

    const int t = threadIdx.x;
    for (int i = t; i < OUTC * C_IN * KW; i += 256) {
        int oc = i / KW, k = i - oc * KW;
        float w = wp[i];
        s_wp2[oc * 6 + k] = pk(w, w);
    }
    if (t < C_IN) { float w = wn[t]; s_wn2[t] = pk(w, w); }
    if (t < OUTC) s_b[t] = bp[t];
    if (t == 0)   s_b[OUTC] = bn[0];
    __syncthreads();

    const int tok = blockIdx.x * 256 + t;
    const int b = tok >> 12;          // H = 4096
    const int h = tok & (HEIGHT - 1);

    const float* xb = x + (size_t)b * (C_IN * HEIGHT * FD) + (size_t)h * FD;

    ull accL[FD / 2];                 // feature pairs (0,1)(2,3)(4,5)(6,7)
    ull accP[OUTC * 2];               // per o: pairs (w0,w1),(w2,w3)
#pragma unroll
    for (int j = 0; j < FD / 2; j++) accL[j] = 0ULL;
#pragma unroll
    for (int e = 0; e < OUTC * 2; e++) accP[e] = 0ULL;

#pragma unroll 4
    for (int c = 0; c < C_IN; c++) {
        const float4* p4 = (const float4*)(xb + (size_t)c * (HEIGHT * FD));
        float4 u = p4[0];
        float4 v = p4[1];
        float xv[8] = {u.x, u.y, u.z, u.w, v.x, v.y, v.z, v.w};
        ull xm[7];                    // xm[m] = (x[m], x[m+1])
#pragma unroll
        for (int m = 0; m < 7; m++) xm[m] = pk(xv[m], xv[m + 1]);

        const ull w0 = s_wn2[c];
#pragma unroll
        for (int j = 0; j < FD / 2; j++) accL[j] = fma2(xm[2 * j], w0, accL[j]);

#pragma unroll
        for (int o = 0; o < OUTC; o++) {
            const ull* wr = s_wp2 + (o * C_IN + c) * 6;
            ulonglong2 wA = *(const ulonglong2*)(wr);      // w0, w1
            ulonglong2 wB = *(const ulonglong2*)(wr + 2);  // w2, w3
            ull w4 = wr[4];
            ull w[KW] = {wA.x, wA.y, wB.x, wB.y, w4};
#pragma unroll
            for (int wp2 = 0; wp2 < 2; wp2++) {
#pragma unroll
                for (int k = 0; k < KW; k++)
                    accP[o * 2 + wp2] = fma2(xm[2 * wp2 + k], w[k], accP[o * 2 + wp2]);
            }
        }
    }

    // epilogue: loc = softplus(acc + b_n)
    const float bnv = s_b[OUTC];
    float r[8];
#pragma unroll
    for (int j = 0; j < FD / 2; j++) {
        float a, bb;
        upk(accL[j], a, bb);
        r[2 * j]     = softplus(a + bnv);
        r[2 * j + 1] = softplus(bb + bnv);
    }
    float4* lp = (float4*)(out_loc + (size_t)tok * FD);
    lp[0] = make_float4(r[0], r[1], r[2], r[3]);
    lp[1] = make_float4(r[4], r[5], r[6], r[7]);

    // sigma entries -> SoA scratch (coalesced: stride-1 in tok)
#pragma unroll
    for (int o = 0; o < OUTC; o++) {
        float be = s_b[o];
        float a, bb;
        upk(accP[o * 2], a, bb);
        g_sigma[(o * 4 + 0) * NTOK + tok] = softplus(a + be);
        g_sigma[(o * 4 + 1) * NTOK + tok] = softplus(bb + be);
        upk(accP[o * 2 + 1], a, bb);
        g_sigma[(o * 4 + 2) * NTOK + tok] = softplus(a + be);
        g_sigma[(o * 4 + 3) * NTOK + tok] = softplus(bb + be);
    }
}

// ---------------------------------------------------------------------------
// Kernel 2: batched 8x8 symmetric eigh via fixed-sweep cyclic Jacobi.
// A kept as 36-entry upper triangle (compile-time-folded indexing).
// Division-free rotation: 2 rsqrt, trace-preserving diagonal update.
// ---------------------------------------------------------------------------
#define TI(i,j) ((i) <= (j) ? ((i)*(17-(i)))/2 + ((j)-(i)) \
                            : ((j)*(17-(j)))/2 + ((i)-(j)))
#define AT(i,j) Au[TI(i,j)]

__global__ void __launch_bounds__(128) eigh_kernel(float* __restrict__ out_pd)
{
    const int tok = blockIdx.x * 128 + threadIdx.x;

    float Au[HALF];
#pragma unroll
    for (int e = 0; e < HALF; e++) Au[e] = g_sigma[e * NTOK + tok];

    float V[8][8];
#pragma unroll
    for (int i = 0; i < 8; i++)
#pragma unroll
        for (int j = 0; j < 8; j++) V[i][j] = (i == j) ? 1.0f : 0.0f;

#pragma unroll 1
    for (int sweep = 0; sweep < NSWEEP; sweep++) {
#pragma unroll
        for (int p = 0; p < 7; p++) {
#pragma unroll
            for (int q = p + 1; q < 8; q++) {
                float apq = AT(p, q);
                float app = AT(p, p);
                float aqq = AT(q, q);
                float tau = (aqq - app);
                tau += copysignf(1e-18f, tau);          // degenerate-safe
                float r2    = fmaf(tau, tau, 4.0f * apq * apq);
                float inv_r = rsqrtf(r2);
                float c2    = fmaf(0.5f * fabsf(tau), inv_r, 0.5f); // cos^2
                float cinv  = rsqrtf(c2);
                float cc    = c2 * cinv;                            // cos
                float st    = (tau < 0.0f) ? -apq : apq;            // sign(tau)*apq
                float ss    = st * inv_r * cinv;                    // sin
                float s2c   = 2.0f * st * inv_r;                    // sin(2phi) fold

                float napp = c2 * app + (1.0f - c2) * aqq - s2c * apq;
                AT(p, p) = napp;
                AT(q, q) = (app + aqq) - napp;
                AT(p, q) = 0.0f;

#pragma unroll
                for (int j = 0; j < 8; j++) {
                    if (j == p || j == q) continue;
                    float ajp = AT(j, p), ajq = AT(j, q);
                    AT(j, p) = cc * ajp - ss * ajq;
                    AT(j, q) = ss * ajp + cc * ajq;
                }
#pragma unroll
                for (int j = 0; j < 8; j++) {
                    float vjp = V[j][p], vjq = V[j][q];
                    V[j][p] = cc * vjp - ss * vjq;
                    V[j][q] = ss * vjp + cc * vjq;
                }
            }
        }
    }

    float lam[8];
#pragma unroll
    for (int k = 0; k < 8; k++) lam[k] = fmaxf(AT(k, k), MIN_EIG);

    float W[8][8];
#pragma unroll
    for (int i = 0; i < 8; i++)
#pragma unroll
        for (int k = 0; k < 8; k++) W[i][k] = V[i][k] * lam[k];

    float pd[8][8];
#pragma unroll
    for (int i = 0; i < 8; i++) {
#pragma unroll
        for (int j = i; j < 8; j++) {
            float acc = 0.0f;
#pragma unroll
            for (int k = 0; k < 8; k++) acc = fmaf(W[i][k], V[j][k], acc);
            pd[i][j] = acc; pd[j][i] = acc;
        }
    }

    float* o = out_pd + (size_t)tok * 64;
#pragma unroll
    for (int i = 0; i < 8; i++) {
        ((float4*)o)[i * 2]     = make_float4(pd[i][0], pd[i][1], pd[i][2], pd[i][3]);
        ((float4*)o)[i * 2 + 1] = make_float4(pd[i][4], pd[i][5], pd[i][6], pd[i][7]);
    }
}

// ---------------------------------------------------------------------------
extern "C" void kernel_launch(void* const* d_in, const int* in_sizes, int n_in,
                              void* d_out, int out_size)
{
    // Identify inputs by element count (robust to metadata ordering):
    // x: 67108864, w_n: 64, b_n: 1, w_p: 2880, b_p: 9
    const float* x  = nullptr;
    const float* wn = nullptr;
    const float* bn = nullptr;
    const float* wp = nullptr;
    const float* bp = nullptr;
    for (int i = 0; i < n_in; i++) {
        switch (in_sizes[i]) {
            case 64:    wn = (const float*)d_in[i]; break;
            case 1:     bn = (const float*)d_in[i]; break;
            case 2880:  wp = (const float*)d_in[i]; break;
            case 9:     bp = (const float*)d_in[i]; break;
            default:    x  = (const float*)d_in[i]; break;
        }
    }

    float* out = (float*)d_out;
    float* loc = out;                                            // [B,1,H,FD]
    float* pd  = out + ((size_t)out_size - (size_t)NTOK * 64);   // [B,1,H,8,8]

    conv_kernel<<<NTOK / 256, 256>>>(x, wn, bn, wp, bp, loc);
    eigh_kernel<<<NTOK / 128, 128>>>(pd);
}